// round 13
// baseline (speedup 1.0000x reference)
#include <cuda_runtime.h>
#include <cuda_fp16.h>
#include <math.h>
#include <stdint.h>

#define MAXN 100000
#define MAXE 1600000
#define HDIM 128
#define CDIM 40
#define NBLK ((MAXN + 255) / 256)
#define PAD 136  // halves per smem row (128 + 8 pad -> conflict-free ldmatrix)

// ---------------- device scratch ----------------
__device__ uint8_t g_lin8[MAXN * HDIM];       // norm[row]*(h@W) in fp8 e4m3 (gather payload)
__device__ __half  g_hh[MAXN * HDIM];         // layer output (post-ReLU) fp16
__device__ float   g_norm[MAXN];
__device__ int     g_deg[MAXN];
__device__ int     g_rowstart[MAXN + 1];
__device__ int     g_cursor[MAXN];
__device__ int     g_bsum[NBLK + 1];
__device__ int     g_csrS[MAXE];              // src index per edge, grouped by dst
__device__ float   g_bf[CDIM];
__device__ int     g_any;                     // starts 0; reset at end of each run
__device__ __half  g_Wh[4 * HDIM * HDIM];     // W^T fp16 hi images (3 layers + head)
__device__ __half  g_Wl[4 * HDIM * HDIM];     // fp16( 2048*(W - hi) ) (head uses slot 3)

// ---------------- PTX helpers ----------------
__device__ __forceinline__ uint32_t smem_u32(const void* p) {
    uint32_t a;
    asm("{ .reg .u64 t; cvta.to.shared.u64 t, %1; cvt.u32.u64 %0, t; }" : "=r"(a) : "l"(p));
    return a;
}
__device__ __forceinline__ void ldx4(uint32_t* r, uint32_t addr) {
    asm volatile("ldmatrix.sync.aligned.m8n8.x4.shared.b16 {%0,%1,%2,%3}, [%4];"
                 : "=r"(r[0]), "=r"(r[1]), "=r"(r[2]), "=r"(r[3]) : "r"(addr));
}
__device__ __forceinline__ void mma_f16(float* d, const uint32_t* a, const uint32_t* b) {
    asm volatile("mma.sync.aligned.m16n8k16.row.col.f32.f16.f16.f32 "
                 "{%0,%1,%2,%3}, {%4,%5,%6,%7}, {%8,%9}, {%0,%1,%2,%3};"
                 : "+f"(d[0]), "+f"(d[1]), "+f"(d[2]), "+f"(d[3])
                 : "r"(a[0]), "r"(a[1]), "r"(a[2]), "r"(a[3]), "r"(b[0]), "r"(b[1]));
}
// pack two floats into e4m3x2 (a -> low byte, b -> high byte)
__device__ __forceinline__ uint16_t pack_e4m3(float a, float b) {
    uint16_t r;
    asm("cvt.rn.satfinite.e4m3x2.f32 %0, %1, %2;" : "=h"(r) : "f"(b), "f"(a));
    return r;
}
// unpack e4m3x2 -> half2 (low byte -> x)
__device__ __forceinline__ __half2 unpack_e4m3(uint16_t v) {
    uint32_t h2;
    asm("cvt.rn.f16x2.e4m3x2 %0, %1;" : "=r"(h2) : "h"(v));
    return *(__half2*)&h2;
}
__device__ __forceinline__ int load_node(const void* ei, long long i, int is64) {
    if (is64) return (int)((const long long*)ei)[i];
    return ((const int*)ei)[i];
}

// ---------------- merged prep: deg zero + dtype detect + W splits + head fold ----------------
__global__ void prep_kernel(const int* __restrict__ ei32, int M, int nHalf,
                            const float* __restrict__ W1, const float* __restrict__ W2,
                            const float* __restrict__ W3,
                            const float* __restrict__ Wp1, const float* __restrict__ bp1,
                            const float* __restrict__ Wp2, const float* __restrict__ bp2)
{
    int i = blockIdx.x * blockDim.x + threadIdx.x;
    if (i < M) g_deg[i] = 0;

    int found = 0;
    for (int j = i; j < nHalf; j += gridDim.x * blockDim.x)
        if (ei32[2 * j + 1] != 0) found = 1;
    if (found) atomicOr(&g_any, 1);

    if (i < 3 * HDIM * HDIM) {
        int l = i / (HDIM * HDIM);
        int r = i - l * HDIM * HDIM;
        int n = r >> 7, k = r & 127;
        const float* W = (l == 0) ? W1 : (l == 1) ? W2 : W3;
        g_Wh[i] = __float2half_rn(W[k * HDIM + n]);   // layers: single-term fp16
    } else if (i < 4 * HDIM * HDIM) {
        int id = i - 3 * HDIM * HDIM;
        int n = id >> 7, k = id & 127;
        float v = 0.f;
        if (n < CDIM) {
            for (int j = 0; j < HDIM; j++)
                v = fmaf(Wp1[k * HDIM + j], Wp2[j * CDIM + n], v);
        }
        __half h = __float2half_rn(v);
        g_Wh[3 * HDIM * HDIM + id] = h;
        g_Wl[3 * HDIM * HDIM + id] = __float2half_rn((v - __half2float(h)) * 2048.0f);
    } else if (i < 4 * HDIM * HDIM + CDIM) {
        int c = i - 4 * HDIM * HDIM;
        float s = bp2[c];
        for (int j = 0; j < HDIM; j++)
            s = fmaf(bp1[j], Wp2[j * CDIM + c], s);
        g_bf[c] = s;
    }
}

__global__ void count_deg_kernel(const void* __restrict__ ei, int E) {
    int is64 = (g_any == 0);
    int e = blockIdx.x * blockDim.x + threadIdx.x;
    if (e >= E) return;
    atomicAdd(&g_deg[load_node(ei, (long long)E + e, is64)], 1);
}
__global__ void norm_bsum_kernel(int M) {
    __shared__ int sd[256];
    int i = blockIdx.x * 256 + threadIdx.x;
    int d = (i < M) ? g_deg[i] : 0;
    if (i < M) g_norm[i] = rsqrtf((float)d + 1.0f);
    sd[threadIdx.x] = d;
    __syncthreads();
    for (int o = 128; o > 0; o >>= 1) {
        if (threadIdx.x < o) sd[threadIdx.x] += sd[threadIdx.x + o];
        __syncthreads();
    }
    if (threadIdx.x == 0) g_bsum[blockIdx.x] = sd[0];
}
__global__ void rowstart_kernel(int M, int E) {
    __shared__ int sd[256];
    __shared__ int spre[256];
    int t = threadIdx.x;
    int pre = 0;
    for (int j = t; j < blockIdx.x; j += 256) pre += g_bsum[j];
    spre[t] = pre;
    __syncthreads();
    for (int o = 128; o > 0; o >>= 1) {
        if (t < o) spre[t] += spre[t + o];
        __syncthreads();
    }
    int blockBase = spre[0];

    int i = blockIdx.x * 256 + t;
    int v = (i < M) ? g_deg[i] : 0;
    sd[t] = v;
    __syncthreads();
    for (int o = 1; o < 256; o <<= 1) {
        int x = (t >= o) ? sd[t - o] : 0;
        __syncthreads();
        sd[t] += x;
        __syncthreads();
    }
    if (i < M) {
        g_rowstart[i] = blockBase + sd[t] - v;
        g_cursor[i] = 0;
    }
    if (i == 0) g_rowstart[M] = E;
}
__global__ void csr_fill_kernel(const void* __restrict__ ei, int E) {
    int is64 = (g_any == 0);
    int e = blockIdx.x * blockDim.x + threadIdx.x;
    if (e >= E) return;
    int s = load_node(ei, e, is64);
    int d = load_node(ei, (long long)E + e, is64);
    int pos = g_rowstart[d] + atomicAdd(&g_cursor[d], 1);
    g_csrS[pos] = s;
}

// ---------------- mma.sync GEMM ----------------
// terms=1: D = A·Wh (layers).  terms=2: D = A·Wh + (A*2^-11)·(Wl*2^11) (head).
// mode 0: writes g_lin8 = fp8(norm[row]*(A@W)).  mode 1: head logits + log_softmax -> out.
#define GEMM_SMEM_L (2 * 128 * PAD * 2)   // sA + sBh
#define GEMM_SMEM_H (3 * 128 * PAD * 2)   // sA + sBh + sBl

__global__ __launch_bounds__(256, 2) void mma_gemm_kernel(
    const float* __restrict__ A_ext, float* __restrict__ out,
    int M, int useInternal, int bsel, int mode, int terms)
{
    extern __shared__ __half sm[];
    __half* sA  = sm;                 // [128][PAD] fp16
    __half* sBh = sm + 128 * PAD;
    __half* sBl = sm + 2 * 128 * PAD; // only when terms==2
    const __half* Bh = g_Wh + bsel * HDIM * HDIM;
    const __half* Bl = g_Wl + bsel * HDIM * HDIM;

    int tid = threadIdx.x;
    int rowBase = blockIdx.x * 128;

    {
        const uint4* bh = (const uint4*)Bh;
        for (int i = tid; i < 128 * 16; i += 256) {
            int n = i >> 4, c = i & 15;
            *(uint4*)(sBh + n * PAD + c * 8) = bh[i];
        }
        if (terms == 2) {
            const uint4* bl = (const uint4*)Bl;
            for (int i = tid; i < 128 * 16; i += 256) {
                int n = i >> 4, c = i & 15;
                *(uint4*)(sBl + n * PAD + c * 8) = bl[i];
            }
        }
    }
    {
        int row = tid >> 1;
        int colBase = (tid & 1) * 64;
        int grow = rowBase + row;
        __half* dst = sA + row * PAD + colBase;
        if (useInternal) {
            const uint4* Ap = (const uint4*)(g_hh + (size_t)grow * HDIM + colBase);
            #pragma unroll
            for (int j = 0; j < 8; j++) {
                uint4 v = make_uint4(0u, 0u, 0u, 0u);
                if (grow < M) v = Ap[j];
                *(uint4*)(dst + j * 8) = v;
            }
        } else {
            const float4* Ap = (const float4*)(A_ext + (size_t)grow * HDIM + colBase);
            #pragma unroll
            for (int j = 0; j < 16; j++) {
                float4 v = make_float4(0.f, 0.f, 0.f, 0.f);
                if (grow < M) v = Ap[j];
                __half2 h01 = __floats2half2_rn(v.x, v.y);
                __half2 h23 = __floats2half2_rn(v.z, v.w);
                *(__half2*)(dst + j * 4)     = h01;
                *(__half2*)(dst + j * 4 + 2) = h23;
            }
        }
    }
    __syncthreads();

    int lane = tid & 31, wid = tid >> 5;
    int wm = (wid & 3) * 32;
    int wn = (wid >> 2) * 64;

    uint32_t sbase = smem_u32(sm);
    int a_r = lane & 15;
    int a_k = (lane >> 4) * 8;
    int b_n = ((lane >> 4) & 1) * 8 + (lane & 7);
    int b_k = ((lane >> 3) & 1) * 8;

    uint32_t aA  = sbase + ((wm + a_r) * PAD + a_k) * 2;
    uint32_t aBh = sbase + 128 * PAD * 2 + ((wn + b_n) * PAD + b_k) * 2;
    uint32_t aBl = aBh + 128 * PAD * 2;

    const __half2 SC = __float2half2_rn(4.8828125e-4f);  // 2^-11
    const uint32_t scu = *(const uint32_t*)&SC;

    float d[2][8][4];
    #pragma unroll
    for (int mt = 0; mt < 2; mt++)
        #pragma unroll
        for (int nt = 0; nt < 8; nt++)
            #pragma unroll
            for (int r = 0; r < 4; r++) d[mt][nt][r] = 0.f;

    // head (mode 1): only cols < 64 hold data; wn==64 warps skip MMA entirely
    if (mode == 0 || wn == 0) {
        #pragma unroll
        for (int ks = 0; ks < 8; ks++) {
            uint32_t a[2][4], b[4][4];
            uint32_t koff = (uint32_t)(ks * 16 * 2);
            #pragma unroll
            for (int mt = 0; mt < 2; mt++)
                ldx4(a[mt], aA + (uint32_t)(mt * 16 * PAD * 2) + koff);
            #pragma unroll
            for (int np = 0; np < 4; np++)
                ldx4(b[np], aBh + (uint32_t)(np * 16 * PAD * 2) + koff);
            #pragma unroll
            for (int mt = 0; mt < 2; mt++)
                #pragma unroll
                for (int nt = 0; nt < 8; nt++)
                    mma_f16(d[mt][nt], a[mt], &b[nt >> 1][(nt & 1) * 2]);
            if (terms == 2) {
                uint32_t as[2][4];
                #pragma unroll
                for (int mt = 0; mt < 2; mt++)
                    #pragma unroll
                    for (int r = 0; r < 4; r++) {
                        __half2 av = *(__half2*)&a[mt][r];
                        __half2 sv = __hmul2(av, *(const __half2*)&scu);
                        as[mt][r] = *(uint32_t*)&sv;
                    }
                #pragma unroll
                for (int np = 0; np < 4; np++)
                    ldx4(b[np], aBl + (uint32_t)(np * 16 * PAD * 2) + koff);
                #pragma unroll
                for (int mt = 0; mt < 2; mt++)
                    #pragma unroll
                    for (int nt = 0; nt < 8; nt++)
                        mma_f16(d[mt][nt], as[mt], &b[nt >> 1][(nt & 1) * 2]);
            }
        }
    }

    int g = lane >> 2, t2 = (lane & 3) * 2;
    if (mode == 0) {
        #pragma unroll
        for (int mt = 0; mt < 2; mt++) {
            int r0 = rowBase + wm + mt * 16 + g;
            int r1 = r0 + 8;
            float n0 = (r0 < M) ? g_norm[r0] : 0.f;
            float n1 = (r1 < M) ? g_norm[r1] : 0.f;
            #pragma unroll
            for (int nt = 0; nt < 8; nt++) {
                int col = wn + nt * 8 + t2;
                if (r0 < M) {
                    uint16_t pv = pack_e4m3(d[mt][nt][0] * n0, d[mt][nt][1] * n0);
                    *(uint16_t*)&g_lin8[(size_t)r0 * HDIM + col] = pv;
                }
                if (r1 < M) {
                    uint16_t pv = pack_e4m3(d[mt][nt][2] * n1, d[mt][nt][3] * n1);
                    *(uint16_t*)&g_lin8[(size_t)r1 * HDIM + col] = pv;
                }
            }
        }
    } else {
        if (wn == 0) {
            float bv[5][2];
            #pragma unroll
            for (int nt = 0; nt < 5; nt++) {
                int col = nt * 8 + t2;
                bv[nt][0] = __ldg(g_bf + col);
                bv[nt][1] = __ldg(g_bf + col + 1);
            }
            #pragma unroll
            for (int mt = 0; mt < 2; mt++) {
                #pragma unroll
                for (int half = 0; half < 2; half++) {
                    int row = rowBase + wm + mt * 16 + g + half * 8;
                    int ri = half * 2;
                    float l[5][2];
                    float m = -1e30f;
                    #pragma unroll
                    for (int nt = 0; nt < 5; nt++) {
                        l[nt][0] = d[mt][nt][ri] + bv[nt][0];
                        l[nt][1] = d[mt][nt][ri + 1] + bv[nt][1];
                        m = fmaxf(m, fmaxf(l[nt][0], l[nt][1]));
                    }
                    m = fmaxf(m, __shfl_xor_sync(0xffffffffu, m, 1));
                    m = fmaxf(m, __shfl_xor_sync(0xffffffffu, m, 2));
                    float e = 0.f;
                    #pragma unroll
                    for (int nt = 0; nt < 5; nt++)
                        e += expf(l[nt][0] - m) + expf(l[nt][1] - m);
                    e += __shfl_xor_sync(0xffffffffu, e, 1);
                    e += __shfl_xor_sync(0xffffffffu, e, 2);
                    float ls = m + logf(e);
                    if (row < M) {
                        #pragma unroll
                        for (int nt = 0; nt < 5; nt++) {
                            int col = nt * 8 + t2;
                            *(float2*)(out + (size_t)row * CDIM + col) =
                                make_float2(l[nt][0] - ls, l[nt][1] - ls);
                        }
                    }
                }
            }
        }
        if (blockIdx.x == 0 && tid == 0) g_any = 0;
    }
}

// ---------------- gather: h = relu(norm[dst]*(sum fp8 linh[src] + self) + bias), fp16 out ----------------
// One warp per dst row; lane owns 4 features (4B fp8). One 128B line per edge row.
__global__ __launch_bounds__(256) void gather_kernel(const float* __restrict__ bias, int M)
{
    int warp = (blockIdx.x * 256 + threadIdx.x) >> 5;
    int lane = threadIdx.x & 31;
    if (warp >= M) return;
    int row = warp;

    int start = g_rowstart[row];
    int end   = g_rowstart[row + 1];

    const uint32_t* lp = (const uint32_t*)g_lin8;  // 32 x uint32 per row

    uint32_t sv = __ldg(lp + (size_t)row * 32 + lane);
    float2 a01 = __half22float2(unpack_e4m3((uint16_t)(sv & 0xFFFFu)));
    float2 a23 = __half22float2(unpack_e4m3((uint16_t)(sv >> 16)));
    float4 acc = make_float4(a01.x, a01.y, a23.x, a23.y);

    for (int bse = start; bse < end; bse += 32) {
        int idx = bse + lane;
        int sidx = (idx < end) ? g_csrS[idx] : 0;
        int cnt = min(32, end - bse);
        int j = 0;
        for (; j + 3 < cnt; j += 4) {
            uint32_t v[4];
            #pragma unroll
            for (int u = 0; u < 4; u++) {
                int s = __shfl_sync(0xffffffffu, sidx, j + u);
                v[u] = __ldg(lp + (size_t)s * 32 + lane);
            }
            #pragma unroll
            for (int u = 0; u < 4; u++) {
                float2 p = __half22float2(unpack_e4m3((uint16_t)(v[u] & 0xFFFFu)));
                float2 q = __half22float2(unpack_e4m3((uint16_t)(v[u] >> 16)));
                acc.x += p.x; acc.y += p.y; acc.z += q.x; acc.w += q.y;
            }
        }
        for (; j < cnt; j++) {
            int s = __shfl_sync(0xffffffffu, sidx, j);
            uint32_t v0 = __ldg(lp + (size_t)s * 32 + lane);
            float2 p = __half22float2(unpack_e4m3((uint16_t)(v0 & 0xFFFFu)));
            float2 q = __half22float2(unpack_e4m3((uint16_t)(v0 >> 16)));
            acc.x += p.x; acc.y += p.y; acc.z += q.x; acc.w += q.y;
        }
    }

    float n = g_norm[row];
    float4 b4 = ((const float4*)bias)[lane];
    float h0 = fmaxf(fmaf(n, acc.x, b4.x), 0.f);
    float h1 = fmaxf(fmaf(n, acc.y, b4.y), 0.f);
    float h2 = fmaxf(fmaf(n, acc.z, b4.z), 0.f);
    float h3 = fmaxf(fmaf(n, acc.w, b4.w), 0.f);
    uint2 hv;
    *(__half2*)&hv.x = __floats2half2_rn(h0, h1);
    *(__half2*)&hv.y = __floats2half2_rn(h2, h3);
    ((uint2*)g_hh)[(size_t)row * 32 + lane] = hv;
}

// ---------------- launch ----------------
extern "C" void kernel_launch(void* const* d_in, const int* in_sizes, int n_in,
                              void* d_out, int out_size)
{
    const float* x   = (const float*)d_in[0];
    const void*  ei  = d_in[1];
    const float* W1  = (const float*)d_in[2];
    const float* b1  = (const float*)d_in[3];
    const float* W2  = (const float*)d_in[4];
    const float* b2  = (const float*)d_in[5];
    const float* W3  = (const float*)d_in[6];
    const float* b3  = (const float*)d_in[7];
    const float* Wp1 = (const float*)d_in[8];
    const float* bp1 = (const float*)d_in[9];
    const float* Wp2 = (const float*)d_in[10];
    const float* bp2 = (const float*)d_in[11];
    float* out = (float*)d_out;

    int M = in_sizes[0] / HDIM;
    int E = in_sizes[1] / 2;
    int nb = (M + 255) / 256;
    int prepBlocks = nb > 257 ? nb : 257;

    cudaFuncSetAttribute(mma_gemm_kernel,
                         cudaFuncAttributeMaxDynamicSharedMemorySize, GEMM_SMEM_H);

    prep_kernel<<<prepBlocks, 256>>>((const int*)ei, M, E, W1, W2, W3, Wp1, bp1, Wp2, bp2);
    count_deg_kernel<<<(E + 255) / 256, 256>>>(ei, E);
    norm_bsum_kernel<<<nb, 256>>>(M);
    rowstart_kernel<<<nb, 256>>>(M, E);
    csr_fill_kernel<<<(E + 255) / 256, 256>>>(ei, E);

    int gemmGrid   = (M + 127) / 128;
    int gatherGrid = (M + 7) / 8;

    mma_gemm_kernel<<<gemmGrid, 256, GEMM_SMEM_L>>>(x, out, M, 0, 0, 0, 1);
    gather_kernel<<<gatherGrid, 256>>>(b1, M);
    mma_gemm_kernel<<<gemmGrid, 256, GEMM_SMEM_L>>>(nullptr, out, M, 1, 1, 0, 1);
    gather_kernel<<<gatherGrid, 256>>>(b2, M);
    mma_gemm_kernel<<<gemmGrid, 256, GEMM_SMEM_L>>>(nullptr, out, M, 1, 2, 0, 1);
    gather_kernel<<<gatherGrid, 256>>>(b3, M);

    mma_gemm_kernel<<<gemmGrid, 256, GEMM_SMEM_H>>>(nullptr, out, M, 1, 3, 1, 2);
}

// round 14
// speedup vs baseline: 1.0951x; 1.0951x over previous
#include <cuda_runtime.h>
#include <cuda_fp16.h>
#include <math.h>
#include <stdint.h>

#define MAXN 100000
#define MAXE 1600000
#define HDIM 128
#define CDIM 40
#define NBLK ((MAXN + 255) / 256)
#define PAD 136  // halves per smem row (128 + 8 pad -> conflict-free ldmatrix)

// ---------------- device scratch ----------------
__device__ __half  g_linh[MAXN * HDIM];       // norm[row]*(h@W) fp16 (gather payload)
__device__ __half  g_hh[MAXN * HDIM];         // layer output (post-ReLU) fp16
__device__ float   g_norm[MAXN];
__device__ int     g_deg[MAXN];
__device__ int     g_rowstart[MAXN + 1];
__device__ int     g_cursor[MAXN];
__device__ int     g_bsum[NBLK + 1];
__device__ int     g_csrS[MAXE];              // src index per edge, grouped by dst
__device__ float   g_bf[CDIM];
__device__ int     g_any;                     // starts 0; reset at end of each run
__device__ __half  g_Wh[4 * HDIM * HDIM];     // W^T fp16 hi images (3 layers + head)
__device__ __half  g_Wl[4 * HDIM * HDIM];     // fp16( 2048*(W - hi) ) (head uses slot 3)

// ---------------- PTX helpers ----------------
__device__ __forceinline__ uint32_t smem_u32(const void* p) {
    uint32_t a;
    asm("{ .reg .u64 t; cvta.to.shared.u64 t, %1; cvt.u32.u64 %0, t; }" : "=r"(a) : "l"(p));
    return a;
}
__device__ __forceinline__ void ldx4(uint32_t* r, uint32_t addr) {
    asm volatile("ldmatrix.sync.aligned.m8n8.x4.shared.b16 {%0,%1,%2,%3}, [%4];"
                 : "=r"(r[0]), "=r"(r[1]), "=r"(r[2]), "=r"(r[3]) : "r"(addr));
}
__device__ __forceinline__ void mma_f16(float* d, const uint32_t* a, const uint32_t* b) {
    asm volatile("mma.sync.aligned.m16n8k16.row.col.f32.f16.f16.f32 "
                 "{%0,%1,%2,%3}, {%4,%5,%6,%7}, {%8,%9}, {%0,%1,%2,%3};"
                 : "+f"(d[0]), "+f"(d[1]), "+f"(d[2]), "+f"(d[3])
                 : "r"(a[0]), "r"(a[1]), "r"(a[2]), "r"(a[3]), "r"(b[0]), "r"(b[1]));
}
__device__ __forceinline__ int load_node(const void* ei, long long i, int is64) {
    if (is64) return (int)((const long long*)ei)[i];
    return ((const int*)ei)[i];
}

// ---------------- merged prep: deg zero + dtype detect + W splits + head fold ----------------
__global__ void prep_kernel(const int* __restrict__ ei32, int M, int nHalf,
                            const float* __restrict__ W1, const float* __restrict__ W2,
                            const float* __restrict__ W3,
                            const float* __restrict__ Wp1, const float* __restrict__ bp1,
                            const float* __restrict__ Wp2, const float* __restrict__ bp2)
{
    int i = blockIdx.x * blockDim.x + threadIdx.x;
    if (i < M) g_deg[i] = 0;

    int found = 0;
    for (int j = i; j < nHalf; j += gridDim.x * blockDim.x)
        if (ei32[2 * j + 1] != 0) found = 1;
    if (found) atomicOr(&g_any, 1);

    if (i < 3 * HDIM * HDIM) {
        int l = i / (HDIM * HDIM);
        int r = i - l * HDIM * HDIM;
        int n = r >> 7, k = r & 127;
        const float* W = (l == 0) ? W1 : (l == 1) ? W2 : W3;
        g_Wh[i] = __float2half_rn(W[k * HDIM + n]);   // layers: single-term fp16
    } else if (i < 4 * HDIM * HDIM) {
        int id = i - 3 * HDIM * HDIM;
        int n = id >> 7, k = id & 127;
        float v = 0.f;
        if (n < CDIM) {
            for (int j = 0; j < HDIM; j++)
                v = fmaf(Wp1[k * HDIM + j], Wp2[j * CDIM + n], v);
        }
        __half h = __float2half_rn(v);
        g_Wh[3 * HDIM * HDIM + id] = h;
        g_Wl[3 * HDIM * HDIM + id] = __float2half_rn((v - __half2float(h)) * 2048.0f);
    } else if (i < 4 * HDIM * HDIM + CDIM) {
        int c = i - 4 * HDIM * HDIM;
        float s = bp2[c];
        for (int j = 0; j < HDIM; j++)
            s = fmaf(bp1[j], Wp2[j * CDIM + c], s);
        g_bf[c] = s;
    }
}

__global__ void count_deg_kernel(const void* __restrict__ ei, int E) {
    int is64 = (g_any == 0);
    int e = blockIdx.x * blockDim.x + threadIdx.x;
    if (e >= E) return;
    atomicAdd(&g_deg[load_node(ei, (long long)E + e, is64)], 1);
}
__global__ void norm_bsum_kernel(int M) {
    __shared__ int sd[256];
    int i = blockIdx.x * 256 + threadIdx.x;
    int d = (i < M) ? g_deg[i] : 0;
    if (i < M) g_norm[i] = rsqrtf((float)d + 1.0f);
    sd[threadIdx.x] = d;
    __syncthreads();
    for (int o = 128; o > 0; o >>= 1) {
        if (threadIdx.x < o) sd[threadIdx.x] += sd[threadIdx.x + o];
        __syncthreads();
    }
    if (threadIdx.x == 0) g_bsum[blockIdx.x] = sd[0];
}
__global__ void rowstart_kernel(int M, int E) {
    __shared__ int sd[256];
    __shared__ int spre[256];
    int t = threadIdx.x;
    int pre = 0;
    for (int j = t; j < blockIdx.x; j += 256) pre += g_bsum[j];
    spre[t] = pre;
    __syncthreads();
    for (int o = 128; o > 0; o >>= 1) {
        if (t < o) spre[t] += spre[t + o];
        __syncthreads();
    }
    int blockBase = spre[0];

    int i = blockIdx.x * 256 + t;
    int v = (i < M) ? g_deg[i] : 0;
    sd[t] = v;
    __syncthreads();
    for (int o = 1; o < 256; o <<= 1) {
        int x = (t >= o) ? sd[t - o] : 0;
        __syncthreads();
        sd[t] += x;
        __syncthreads();
    }
    if (i < M) {
        g_rowstart[i] = blockBase + sd[t] - v;
        g_cursor[i] = 0;
    }
    if (i == 0) g_rowstart[M] = E;
}
__global__ void csr_fill_kernel(const void* __restrict__ ei, int E) {
    int is64 = (g_any == 0);
    int e = blockIdx.x * blockDim.x + threadIdx.x;
    if (e >= E) return;
    int s = load_node(ei, e, is64);
    int d = load_node(ei, (long long)E + e, is64);
    int pos = g_rowstart[d] + atomicAdd(&g_cursor[d], 1);
    g_csrS[pos] = s;
}

// ---------------- mma.sync GEMM ----------------
// terms=1: D = A·Wh (layers).  terms=2: D = A·Wh + (A*2^-11)·(Wl*2^11) (head).
// mode 0: writes g_linh = fp16(norm[row]*(A@W)).  mode 1: head logits + log_softmax -> out.
#define GEMM_SMEM_L (2 * 128 * PAD * 2)   // sA + sBh
#define GEMM_SMEM_H (3 * 128 * PAD * 2)   // sA + sBh + sBl

__global__ __launch_bounds__(256, 2) void mma_gemm_kernel(
    const float* __restrict__ A_ext, float* __restrict__ out,
    int M, int useInternal, int bsel, int mode, int terms)
{
    extern __shared__ __half sm[];
    __half* sA  = sm;                 // [128][PAD] fp16
    __half* sBh = sm + 128 * PAD;
    __half* sBl = sm + 2 * 128 * PAD; // only when terms==2
    const __half* Bh = g_Wh + bsel * HDIM * HDIM;
    const __half* Bl = g_Wl + bsel * HDIM * HDIM;

    int tid = threadIdx.x;
    int rowBase = blockIdx.x * 128;

    {
        const uint4* bh = (const uint4*)Bh;
        for (int i = tid; i < 128 * 16; i += 256) {
            int n = i >> 4, c = i & 15;
            *(uint4*)(sBh + n * PAD + c * 8) = bh[i];
        }
        if (terms == 2) {
            const uint4* bl = (const uint4*)Bl;
            for (int i = tid; i < 128 * 16; i += 256) {
                int n = i >> 4, c = i & 15;
                *(uint4*)(sBl + n * PAD + c * 8) = bl[i];
            }
        }
    }
    {
        int row = tid >> 1;
        int colBase = (tid & 1) * 64;
        int grow = rowBase + row;
        __half* dst = sA + row * PAD + colBase;
        if (useInternal) {
            const uint4* Ap = (const uint4*)(g_hh + (size_t)grow * HDIM + colBase);
            #pragma unroll
            for (int j = 0; j < 8; j++) {
                uint4 v = make_uint4(0u, 0u, 0u, 0u);
                if (grow < M) v = Ap[j];
                *(uint4*)(dst + j * 8) = v;
            }
        } else {
            const float4* Ap = (const float4*)(A_ext + (size_t)grow * HDIM + colBase);
            #pragma unroll
            for (int j = 0; j < 16; j++) {
                float4 v = make_float4(0.f, 0.f, 0.f, 0.f);
                if (grow < M) v = Ap[j];
                __half2 h01 = __floats2half2_rn(v.x, v.y);
                __half2 h23 = __floats2half2_rn(v.z, v.w);
                *(__half2*)(dst + j * 4)     = h01;
                *(__half2*)(dst + j * 4 + 2) = h23;
            }
        }
    }
    __syncthreads();

    int lane = tid & 31, wid = tid >> 5;
    int wm = (wid & 3) * 32;
    int wn = (wid >> 2) * 64;

    uint32_t sbase = smem_u32(sm);
    int a_r = lane & 15;
    int a_k = (lane >> 4) * 8;
    int b_n = ((lane >> 4) & 1) * 8 + (lane & 7);
    int b_k = ((lane >> 3) & 1) * 8;

    uint32_t aA  = sbase + ((wm + a_r) * PAD + a_k) * 2;
    uint32_t aBh = sbase + 128 * PAD * 2 + ((wn + b_n) * PAD + b_k) * 2;
    uint32_t aBl = aBh + 128 * PAD * 2;

    const __half2 SC = __float2half2_rn(4.8828125e-4f);  // 2^-11
    const uint32_t scu = *(const uint32_t*)&SC;

    float d[2][8][4];
    #pragma unroll
    for (int mt = 0; mt < 2; mt++)
        #pragma unroll
        for (int nt = 0; nt < 8; nt++)
            #pragma unroll
            for (int r = 0; r < 4; r++) d[mt][nt][r] = 0.f;

    // head (mode 1): only cols < 64 hold data; wn==64 warps skip MMA entirely
    if (mode == 0 || wn == 0) {
        #pragma unroll
        for (int ks = 0; ks < 8; ks++) {
            uint32_t a[2][4], b[4][4];
            uint32_t koff = (uint32_t)(ks * 16 * 2);
            #pragma unroll
            for (int mt = 0; mt < 2; mt++)
                ldx4(a[mt], aA + (uint32_t)(mt * 16 * PAD * 2) + koff);
            #pragma unroll
            for (int np = 0; np < 4; np++)
                ldx4(b[np], aBh + (uint32_t)(np * 16 * PAD * 2) + koff);
            #pragma unroll
            for (int mt = 0; mt < 2; mt++)
                #pragma unroll
                for (int nt = 0; nt < 8; nt++)
                    mma_f16(d[mt][nt], a[mt], &b[nt >> 1][(nt & 1) * 2]);
            if (terms == 2) {
                uint32_t as[2][4];
                #pragma unroll
                for (int mt = 0; mt < 2; mt++)
                    #pragma unroll
                    for (int r = 0; r < 4; r++) {
                        __half2 av = *(__half2*)&a[mt][r];
                        __half2 sv = __hmul2(av, *(const __half2*)&scu);
                        as[mt][r] = *(uint32_t*)&sv;
                    }
                #pragma unroll
                for (int np = 0; np < 4; np++)
                    ldx4(b[np], aBl + (uint32_t)(np * 16 * PAD * 2) + koff);
                #pragma unroll
                for (int mt = 0; mt < 2; mt++)
                    #pragma unroll
                    for (int nt = 0; nt < 8; nt++)
                        mma_f16(d[mt][nt], as[mt], &b[nt >> 1][(nt & 1) * 2]);
            }
        }
    }

    int g = lane >> 2, t2 = (lane & 3) * 2;
    if (mode == 0) {
        #pragma unroll
        for (int mt = 0; mt < 2; mt++) {
            int r0 = rowBase + wm + mt * 16 + g;
            int r1 = r0 + 8;
            float n0 = (r0 < M) ? g_norm[r0] : 0.f;
            float n1 = (r1 < M) ? g_norm[r1] : 0.f;
            #pragma unroll
            for (int nt = 0; nt < 8; nt++) {
                int col = wn + nt * 8 + t2;
                if (r0 < M) {
                    __half2 hv = __floats2half2_rn(d[mt][nt][0] * n0, d[mt][nt][1] * n0);
                    *(__half2*)&g_linh[(size_t)r0 * HDIM + col] = hv;
                }
                if (r1 < M) {
                    __half2 hv = __floats2half2_rn(d[mt][nt][2] * n1, d[mt][nt][3] * n1);
                    *(__half2*)&g_linh[(size_t)r1 * HDIM + col] = hv;
                }
            }
        }
    } else {
        if (wn == 0) {
            float bv[5][2];
            #pragma unroll
            for (int nt = 0; nt < 5; nt++) {
                int col = nt * 8 + t2;
                bv[nt][0] = __ldg(g_bf + col);
                bv[nt][1] = __ldg(g_bf + col + 1);
            }
            #pragma unroll
            for (int mt = 0; mt < 2; mt++) {
                #pragma unroll
                for (int half = 0; half < 2; half++) {
                    int row = rowBase + wm + mt * 16 + g + half * 8;
                    int ri = half * 2;
                    float l[5][2];
                    float m = -1e30f;
                    #pragma unroll
                    for (int nt = 0; nt < 5; nt++) {
                        l[nt][0] = d[mt][nt][ri] + bv[nt][0];
                        l[nt][1] = d[mt][nt][ri + 1] + bv[nt][1];
                        m = fmaxf(m, fmaxf(l[nt][0], l[nt][1]));
                    }
                    m = fmaxf(m, __shfl_xor_sync(0xffffffffu, m, 1));
                    m = fmaxf(m, __shfl_xor_sync(0xffffffffu, m, 2));
                    float e = 0.f;
                    #pragma unroll
                    for (int nt = 0; nt < 5; nt++)
                        e += expf(l[nt][0] - m) + expf(l[nt][1] - m);
                    e += __shfl_xor_sync(0xffffffffu, e, 1);
                    e += __shfl_xor_sync(0xffffffffu, e, 2);
                    float ls = m + logf(e);
                    if (row < M) {
                        #pragma unroll
                        for (int nt = 0; nt < 5; nt++) {
                            int col = nt * 8 + t2;
                            *(float2*)(out + (size_t)row * CDIM + col) =
                                make_float2(l[nt][0] - ls, l[nt][1] - ls);
                        }
                    }
                }
            }
        }
        if (blockIdx.x == 0 && tid == 0) g_any = 0;
    }
}

// ---------------- gather: 2 rows per warp (half-warp x uint4), half2 accumulation ----------------
// h[row] = relu(norm[row]*(sum linh[src] + linh[row]) + bias), fp16 out.
__global__ __launch_bounds__(256) void gather_kernel(const float* __restrict__ bias, int M)
{
    int pairIdx = (blockIdx.x * 256 + threadIdx.x) >> 5;
    int lane = threadIdx.x & 31;
    int half = lane >> 4;
    int hl = lane & 15;
    int row = pairIdx * 2 + half;
    bool valid = row < M;
    int rv = valid ? row : (M - 1);

    int start = g_rowstart[rv];
    int deg   = valid ? (g_rowstart[rv + 1] - start) : 0;
    int degMax = __reduce_max_sync(0xffffffffu, deg);

    const uint4* lp = (const uint4*)g_linh;  // 16 x uint4 per row

    uint4 sv = __ldg(lp + (size_t)rv * 16 + hl);
    __half2 acc0 = ((__half2*)&sv)[0];
    __half2 acc1 = ((__half2*)&sv)[1];
    __half2 acc2 = ((__half2*)&sv)[2];
    __half2 acc3 = ((__half2*)&sv)[3];

    for (int base = 0; base < degMax; base += 16) {
        int o = base + hl;
        int sidx = (o < deg) ? g_csrS[start + o] : -1;
        int cntMax = min(16, degMax - base);
        #pragma unroll 4
        for (int j = 0; j < cntMax; j++) {
            int src = __shfl_sync(0xffffffffu, sidx, half * 16 + j);
            if (src >= 0) {
                uint4 v = __ldg(lp + (size_t)src * 16 + hl);
                acc0 = __hadd2(acc0, ((__half2*)&v)[0]);
                acc1 = __hadd2(acc1, ((__half2*)&v)[1]);
                acc2 = __hadd2(acc2, ((__half2*)&v)[2]);
                acc3 = __hadd2(acc3, ((__half2*)&v)[3]);
            }
        }
    }

    if (!valid) return;
    float n = g_norm[row];
    const float4* bp = (const float4*)bias;
    float4 bA = bp[hl * 2];
    float4 bB = bp[hl * 2 + 1];
    float2 f0 = __half22float2(acc0);
    float2 f1 = __half22float2(acc1);
    float2 f2 = __half22float2(acc2);
    float2 f3 = __half22float2(acc3);
    float h0 = fmaxf(fmaf(n, f0.x, bA.x), 0.f);
    float h1 = fmaxf(fmaf(n, f0.y, bA.y), 0.f);
    float h2 = fmaxf(fmaf(n, f1.x, bA.z), 0.f);
    float h3 = fmaxf(fmaf(n, f1.y, bA.w), 0.f);
    float h4 = fmaxf(fmaf(n, f2.x, bB.x), 0.f);
    float h5 = fmaxf(fmaf(n, f2.y, bB.y), 0.f);
    float h6 = fmaxf(fmaf(n, f3.x, bB.z), 0.f);
    float h7 = fmaxf(fmaf(n, f3.y, bB.w), 0.f);
    uint4 hv;
    ((__half2*)&hv)[0] = __floats2half2_rn(h0, h1);
    ((__half2*)&hv)[1] = __floats2half2_rn(h2, h3);
    ((__half2*)&hv)[2] = __floats2half2_rn(h4, h5);
    ((__half2*)&hv)[3] = __floats2half2_rn(h6, h7);
    ((uint4*)g_hh)[(size_t)row * 16 + hl] = hv;
}

// ---------------- launch ----------------
extern "C" void kernel_launch(void* const* d_in, const int* in_sizes, int n_in,
                              void* d_out, int out_size)
{
    const float* x   = (const float*)d_in[0];
    const void*  ei  = d_in[1];
    const float* W1  = (const float*)d_in[2];
    const float* b1  = (const float*)d_in[3];
    const float* W2  = (const float*)d_in[4];
    const float* b2  = (const float*)d_in[5];
    const float* W3  = (const float*)d_in[6];
    const float* b3  = (const float*)d_in[7];
    const float* Wp1 = (const float*)d_in[8];
    const float* bp1 = (const float*)d_in[9];
    const float* Wp2 = (const float*)d_in[10];
    const float* bp2 = (const float*)d_in[11];
    float* out = (float*)d_out;

    int M = in_sizes[0] / HDIM;
    int E = in_sizes[1] / 2;
    int nb = (M + 255) / 256;
    int prepBlocks = nb > 257 ? nb : 257;

    cudaFuncSetAttribute(mma_gemm_kernel,
                         cudaFuncAttributeMaxDynamicSharedMemorySize, GEMM_SMEM_H);

    prep_kernel<<<prepBlocks, 256>>>((const int*)ei, M, E, W1, W2, W3, Wp1, bp1, Wp2, bp2);
    count_deg_kernel<<<(E + 255) / 256, 256>>>(ei, E);
    norm_bsum_kernel<<<nb, 256>>>(M);
    rowstart_kernel<<<nb, 256>>>(M, E);
    csr_fill_kernel<<<(E + 255) / 256, 256>>>(ei, E);

    int gemmGrid   = (M + 127) / 128;
    int pairs      = (M + 1) / 2;
    int gatherGrid = (pairs + 7) / 8;

    mma_gemm_kernel<<<gemmGrid, 256, GEMM_SMEM_L>>>(x, out, M, 0, 0, 0, 1);
    gather_kernel<<<gatherGrid, 256>>>(b1, M);
    mma_gemm_kernel<<<gemmGrid, 256, GEMM_SMEM_L>>>(nullptr, out, M, 1, 1, 0, 1);
    gather_kernel<<<gatherGrid, 256>>>(b2, M);
    mma_gemm_kernel<<<gemmGrid, 256, GEMM_SMEM_L>>>(nullptr, out, M, 1, 2, 0, 1);
    gather_kernel<<<gatherGrid, 256>>>(b3, M);

    mma_gemm_kernel<<<gemmGrid, 256, GEMM_SMEM_H>>>(nullptr, out, M, 1, 3, 1, 2);
}